// round 2
// baseline (speedup 1.0000x reference)
#include <cuda_runtime.h>

#define BB 4
#define CC 16
#define HH 384
#define WW 384
#define NPIX (HH*WW)
#define IMG  (BB*NPIX)
#define WSN  (BB*CC*NPIX)

// ---------------- device scratch (allowed: __device__ globals) ----------------
__device__ float2 g_ws[WSN];     // [B,C,H,W] complex workspace
__device__ float2 g_p [IMG];
__device__ float2 g_r [IMG];
__device__ float2 g_Ap[IMG];
__device__ float  g_part[BB*HH]; // per-row reduction partials
__device__ float  g_rtr [BB];
__device__ float  g_alpha[BB];
__device__ float  g_beta [BB];
__device__ float2 g_tw[384];     // e^{-2*pi*i*k/384}

// ---------------- complex helpers ----------------
__device__ __forceinline__ float2 cadd(float2 a, float2 b){ return make_float2(a.x+b.x, a.y+b.y); }
__device__ __forceinline__ float2 csub(float2 a, float2 b){ return make_float2(a.x-b.x, a.y-b.y); }
__device__ __forceinline__ float2 cmul(float2 a, float2 b){
    return make_float2(fmaf(a.x,b.x,-a.y*b.y), fmaf(a.x,b.y, a.y*b.x));
}
template<bool INV>
__device__ __forceinline__ float2 ldtw(int i){
    float2 t = g_tw[i];
    if (INV) t.y = -t.y;
    return t;
}

__global__ void k_init_tw(){
    int k = threadIdx.x; // 0..383
    float s, c;
    sincospif((float)k / 192.0f, &s, &c); // angle = pi*k/192 = 2*pi*k/384
    g_tw[k] = make_float2(c, -s);
}

// ---------------- 384-pt FFT: warp holds 384 complex (12/lane) -----------------
// Input : v[j] = x[lane + 32*j]  (natural order)
// Output: lane holds X[12*bitrev5(lane) + m] in v[m]
// INV=false: exp(-i...), INV=true: exp(+i...). Unnormalized both ways.
template<bool INV>
__device__ __forceinline__ void fft384(float2 v[12], int lane){
    float2 Y[12];
    // per-lane DFT-12 over j: 12 = 4*3 (CT): j = 3a + r
    #pragma unroll
    for (int r = 0; r < 3; r++){
        float2 x0 = v[r], x1 = v[r+3], x2 = v[r+6], x3 = v[r+9];
        float2 t0 = cadd(x0,x2), t1 = csub(x0,x2);
        float2 t2 = cadd(x1,x3), t3 = csub(x1,x3);
        float2 jt3 = INV ? make_float2(-t3.y, t3.x) : make_float2(t3.y, -t3.x);
        Y[4*r+0] = cadd(t0,t2);
        Y[4*r+1] = cadd(t1,jt3);
        Y[4*r+2] = csub(t0,t2);
        Y[4*r+3] = csub(t1,jt3);
    }
    // radix-3 combine with twiddles w3^(r*m) folded via table, + step-2 twiddle lane*m
    #pragma unroll
    for (int m = 0; m < 12; m++){
        int q = m & 3;
        float2 w1 = ldtw<INV>((32*m) % 384);
        float2 w2 = ldtw<INV>((64*m) % 384);
        float2 z  = cadd(Y[q], cadd(cmul(w1, Y[4+q]), cmul(w2, Y[8+q])));
        v[m] = cmul(ldtw<INV>(lane*m), z);   // lane*m <= 31*11 = 341 < 384
    }
    // cross-lane 32-pt Gentleman-Sande DIF via shuffles (lanes end bit-reversed)
    #pragma unroll
    for (int st = 0; st < 5; st++){
        int h = 16 >> st;
        float2 wst = ldtw<INV>((lane & (h-1)) * (192/h));
        bool up = (lane & h) != 0;
        #pragma unroll
        for (int m = 0; m < 12; m++){
            float ox = __shfl_xor_sync(0xffffffffu, v[m].x, h);
            float oy = __shfl_xor_sync(0xffffffffu, v[m].y, h);
            float2 o = make_float2(ox, oy);
            float2 s = up ? csub(o, v[m]) : cadd(v[m], o);
            v[m] = up ? cmul(s, wst) : s;
        }
    }
}
__device__ __forceinline__ int kbase_of(int lane){ return 12 * (int)(__brev((unsigned)lane) >> 27); }

// block reduce (nwarp <= 12), valid result in thread 0
__device__ __forceinline__ float block_reduce(float v, float* sred, int nwarp){
    int lane = threadIdx.x & 31, w = threadIdx.x >> 5;
    #pragma unroll
    for (int o = 16; o; o >>= 1) v += __shfl_down_sync(0xffffffffu, v, o);
    if (lane == 0) sred[w] = v;
    __syncthreads();
    v = 0.f;
    if (w == 0 && lane < nwarp) v = sred[lane];
    if (w == 0){
        #pragma unroll
        for (int o = 16; o; o >>= 1) v += __shfl_down_sync(0xffffffffu, v, o);
    }
    return v;
}

// ---------------- pass1: ws[b,c,h,:] = FFT_W( s[b,c,h,:] * p[b,h,:] ) ----------------
__global__ void __launch_bounds__(256) k_pass1(const float* __restrict__ sre,
                                               const float* __restrict__ sim){
    int wid = threadIdx.x >> 5, lane = threadIdx.x & 31;
    int rid = blockIdx.x * 8 + wid;           // [0, B*C*H)
    int h = rid % HH; int bc = rid / HH; int b = bc / CC;
    int base  = rid * WW;
    int pbase = (b * HH + h) * WW;
    float2 v[12];
    #pragma unroll
    for (int j = 0; j < 12; j++){
        int w = lane + 32*j;
        float2 pv = g_p[pbase + w];
        v[j] = cmul(pv, make_float2(sre[base+w], sim[base+w]));
    }
    fft384<false>(v, lane);
    int kb = kbase_of(lane);
    #pragma unroll
    for (int m = 0; m < 12; m++) g_ws[base + kb + m] = v[m];
}

// ---------------- pass2: per column: FFT_H -> *mask -> IFFT_H (in-place on ws) -------
__global__ void __launch_bounds__(256) k_pass2(const float* __restrict__ mask){
    __shared__ float sR[384*9], sI[384*9];    // 8 cols, stride 9 (bank-conflict-free)
    int tid = threadIdx.x;
    int blk = blockIdx.x;                     // [0, B*C*48)
    int w0 = (blk % 48) * 8;
    int bc = blk / 48; int b = bc / CC;
    int basebc = bc * NPIX;
    for (int idx = tid; idx < 384*8; idx += 256){
        int h = idx >> 3, cl = idx & 7;
        float2 val = g_ws[basebc + h*WW + w0 + cl];
        sR[h*9+cl] = val.x; sI[h*9+cl] = val.y;
    }
    __syncthreads();
    int wrp = tid >> 5, lane = tid & 31;      // warp wrp owns column w0+wrp
    float2 v[12];
    #pragma unroll
    for (int j = 0; j < 12; j++){
        int h = lane + 32*j;
        v[j] = make_float2(sR[h*9+wrp], sI[h*9+wrp]);
    }
    fft384<false>(v, lane);
    int kb = kbase_of(lane);
    #pragma unroll
    for (int m = 0; m < 12; m++){
        float mv = mask[(b*HH + kb + m)*WW + w0 + wrp];
        v[m].x *= mv; v[m].y *= mv;
    }
    __syncwarp();
    #pragma unroll
    for (int m = 0; m < 12; m++){ sR[(kb+m)*9+wrp] = v[m].x; sI[(kb+m)*9+wrp] = v[m].y; }
    __syncwarp();
    #pragma unroll
    for (int j = 0; j < 12; j++){
        int h = lane + 32*j;
        v[j] = make_float2(sR[h*9+wrp], sI[h*9+wrp]);
    }
    fft384<true>(v, lane);
    __syncwarp();
    #pragma unroll
    for (int m = 0; m < 12; m++){ sR[(kb+m)*9+wrp] = v[m].x; sI[(kb+m)*9+wrp] = v[m].y; }
    __syncthreads();
    for (int idx = tid; idx < 384*8; idx += 256){
        int h = idx >> 3, cl = idx & 7;
        g_ws[basebc + h*WW + w0 + cl] = make_float2(sR[h*9+cl], sI[h*9+cl]);
    }
}

// ---------------- pass3: Ap = (1/HW)*sum_c conj(s)*IFFT_W(ws) + lam*p; pAp partial ----
__global__ void __launch_bounds__(256) k_pass3(const float* __restrict__ sre,
                                               const float* __restrict__ sim,
                                               const float* __restrict__ lam_p){
    __shared__ float aR[8*384], aI[8*384];
    __shared__ float sred[16];
    int tid = threadIdx.x, wrp = tid >> 5, lane = tid & 31;
    int bh = blockIdx.x;                      // [0, B*H)
    int b = bh / HH, h = bh % HH;
    int kb = kbase_of(lane);
    float2 acc[12];
    #pragma unroll
    for (int m = 0; m < 12; m++) acc[m] = make_float2(0.f, 0.f);
    #pragma unroll
    for (int ci = 0; ci < 2; ci++){
        int c = wrp + ci*8;
        int base = ((b*CC + c)*HH + h)*WW;
        float2 v[12];
        #pragma unroll
        for (int j = 0; j < 12; j++) v[j] = g_ws[base + lane + 32*j];
        fft384<true>(v, lane);
        #pragma unroll
        for (int m = 0; m < 12; m++){
            int w = kb + m;
            float2 sv = make_float2(sre[base+w], -sim[base+w]);
            acc[m] = cadd(acc[m], cmul(sv, v[m]));
        }
    }
    #pragma unroll
    for (int m = 0; m < 12; m++){ aR[wrp*384 + kb+m] = acc[m].x; aI[wrp*384 + kb+m] = acc[m].y; }
    __syncthreads();
    float lam = *lam_p;
    float pap = 0.f;
    const float sc = 1.0f / (384.0f * 384.0f);
    for (int t = tid; t < 384; t += 256){
        float ar = 0.f, ai = 0.f;
        #pragma unroll
        for (int wv = 0; wv < 8; wv++){ ar += aR[wv*384+t]; ai += aI[wv*384+t]; }
        int idx = bh*WW + t;
        float2 pv = g_p[idx];
        float2 ap = make_float2(fmaf(lam, pv.x, ar*sc), fmaf(lam, pv.y, ai*sc));
        g_Ap[idx] = ap;
        pap += pv.x*ap.x + pv.y*ap.y;
    }
    float tot = block_reduce(pap, sred, 8);
    if (tid == 0) g_part[bh] = tot;
}

// ---------------- rhs pass 1: ws = IFFT_H( y * mask ) (columns) ----------------
__global__ void __launch_bounds__(256) k_rhs1(const float* __restrict__ yre,
                                              const float* __restrict__ yim,
                                              const float* __restrict__ mask){
    __shared__ float sR[384*9], sI[384*9];
    int tid = threadIdx.x;
    int blk = blockIdx.x;
    int w0 = (blk % 48) * 8;
    int bc = blk / 48; int b = bc / CC;
    int basebc = bc * NPIX;
    for (int idx = tid; idx < 384*8; idx += 256){
        int h = idx >> 3, cl = idx & 7;
        int g = basebc + h*WW + w0 + cl;
        float mv = mask[(b*HH + h)*WW + w0 + cl];
        sR[h*9+cl] = yre[g]*mv; sI[h*9+cl] = yim[g]*mv;
    }
    __syncthreads();
    int wrp = tid >> 5, lane = tid & 31;
    float2 v[12];
    #pragma unroll
    for (int j = 0; j < 12; j++){
        int h = lane + 32*j;
        v[j] = make_float2(sR[h*9+wrp], sI[h*9+wrp]);
    }
    fft384<true>(v, lane);
    int kb = kbase_of(lane);
    __syncwarp();
    #pragma unroll
    for (int m = 0; m < 12; m++){ sR[(kb+m)*9+wrp] = v[m].x; sI[(kb+m)*9+wrp] = v[m].y; }
    __syncthreads();
    for (int idx = tid; idx < 384*8; idx += 256){
        int h = idx >> 3, cl = idx & 7;
        g_ws[basebc + h*WW + w0 + cl] = make_float2(sR[h*9+cl], sI[h*9+cl]);
    }
}

// ---------------- rhs pass 2: rhs = (1/384)*sum_c conj(s)*IFFT_W(ws) + lam*x0 --------
// also initializes CG state: p = r = rhs, out = 0, |rhs|^2 row partials
__global__ void __launch_bounds__(256) k_rhs2(const float* __restrict__ sre,
                                              const float* __restrict__ sim,
                                              const float* __restrict__ xre,
                                              const float* __restrict__ xim,
                                              const float* __restrict__ lam_p,
                                              float2* __restrict__ out){
    __shared__ float aR[8*384], aI[8*384];
    __shared__ float sred[16];
    int tid = threadIdx.x, wrp = tid >> 5, lane = tid & 31;
    int bh = blockIdx.x;
    int b = bh / HH, h = bh % HH;
    int kb = kbase_of(lane);
    float2 acc[12];
    #pragma unroll
    for (int m = 0; m < 12; m++) acc[m] = make_float2(0.f, 0.f);
    #pragma unroll
    for (int ci = 0; ci < 2; ci++){
        int c = wrp + ci*8;
        int base = ((b*CC + c)*HH + h)*WW;
        float2 v[12];
        #pragma unroll
        for (int j = 0; j < 12; j++) v[j] = g_ws[base + lane + 32*j];
        fft384<true>(v, lane);
        #pragma unroll
        for (int m = 0; m < 12; m++){
            int w = kb + m;
            float2 sv = make_float2(sre[base+w], -sim[base+w]);
            acc[m] = cadd(acc[m], cmul(sv, v[m]));
        }
    }
    #pragma unroll
    for (int m = 0; m < 12; m++){ aR[wrp*384 + kb+m] = acc[m].x; aI[wrp*384 + kb+m] = acc[m].y; }
    __syncthreads();
    float lam = *lam_p;
    float rr = 0.f;
    const float sc = 1.0f / 384.0f;   // ifft rows (1/384) * ifft cols was unnormalized: see note
    for (int t = tid; t < 384; t += 256){
        float ar = 0.f, ai = 0.f;
        #pragma unroll
        for (int wv = 0; wv < 8; wv++){ ar += aR[wv*384+t]; ai += aI[wv*384+t]; }
        int idx = bh*WW + t;
        // total scale: ortho ifft2 = 1/(H*W) * (unnorm inverse in both dims).
        // k_rhs1 did unnormalized col inverse; here unnormalized row inverse.
        // ortho fft2 followed by mask then ortho ifft2 on y means AH(y) needs 1/(384*384)?
        // _AH: ifft2(y*mask, ortho) = (1/384^2)*unnorm_inverse? No: ortho = 1/sqrt(N_total)=1/384.
        // unnorm_inv_total / 384^2 = ifft(numpy 'backward'); ortho = unnorm_inv/384.
        // We applied no normalization in rhs1 and rhs2 ffts -> divide by 384 once here... 
        // (sc set accordingly below in host comment; value 1/384 is wrong only if analysis wrong)
        float2 rhs = make_float2(fmaf(lam, xre[idx], ar*sc), fmaf(lam, xim[idx], ai*sc));
        g_r[idx] = rhs; g_p[idx] = rhs;
        out[idx] = make_float2(0.f, 0.f);
        rr += rhs.x*rhs.x + rhs.y*rhs.y;
    }
    float tot = block_reduce(rr, sred, 8);
    if (tid == 0) g_part[bh] = tot;
}

// ---------------- scalar reductions (deterministic) ----------------
// mode 0: alpha = rtr/pAp ; mode 1: rtr = sum ; mode 2: beta = new/old, rtr = new
__global__ void __launch_bounds__(384) k_reduce(int mode){
    __shared__ float sred[16];
    int b = blockIdx.x;
    float v = g_part[b*HH + threadIdx.x];
    float tot = block_reduce(v, sred, 12);
    if (threadIdx.x == 0){
        if (mode == 0)      g_alpha[b] = g_rtr[b] / tot;
        else if (mode == 1) g_rtr[b] = tot;
        else { g_beta[b] = tot / g_rtr[b]; g_rtr[b] = tot; }
    }
}

// ---------------- CG vector updates ----------------
__global__ void __launch_bounds__(384) k_update_xr(float2* __restrict__ out){
    __shared__ float sred[16];
    int bh = blockIdx.x; int b = bh / HH;
    float a = g_alpha[b];
    int i = bh*WW + threadIdx.x;
    float2 p = g_p[i], ap = g_Ap[i], x = out[i], r = g_r[i];
    x.x = fmaf(a, p.x, x.x);  x.y = fmaf(a, p.y, x.y);
    r.x = fmaf(-a, ap.x, r.x); r.y = fmaf(-a, ap.y, r.y);
    out[i] = x; g_r[i] = r;
    float v = fmaf(r.x, r.x, r.y*r.y);
    float tot = block_reduce(v, sred, 12);
    if (threadIdx.x == 0) g_part[bh] = tot;
}

__global__ void __launch_bounds__(384) k_update_p(){
    int bh = blockIdx.x; int b = bh / HH;
    float be = g_beta[b];
    int i = bh*WW + threadIdx.x;
    float2 r = g_r[i], p = g_p[i];
    g_p[i] = make_float2(fmaf(be, p.x, r.x), fmaf(be, p.y, r.y));
}

// ---------------- launch ----------------
extern "C" void kernel_launch(void* const* d_in, const int* in_sizes, int n_in,
                              void* d_out, int out_size){
    (void)in_sizes; (void)n_in; (void)out_size;
    const float* lam  = (const float*)d_in[0];
    const float* xre  = (const float*)d_in[1];
    const float* xim  = (const float*)d_in[2];
    const float* yre  = (const float*)d_in[3];
    const float* yim  = (const float*)d_in[4];
    const float* sre  = (const float*)d_in[5];
    const float* sim  = (const float*)d_in[6];
    const float* mask = (const float*)d_in[7];
    float2* out = (float2*)d_out;

    k_init_tw<<<1, 384>>>();
    // rhs = AH(y) + lam*x ; init p=r=rhs, out=0, rtr0 partials
    k_rhs1<<<BB*CC*48, 256>>>(yre, yim, mask);
    k_rhs2<<<BB*HH, 256>>>(sre, sim, xre, xim, lam, out);
    k_reduce<<<BB, 384>>>(1);

    for (int it = 0; it < 10; it++){
        // Ap = M(p): A then AH, fused; pAp partials in pass3
        k_pass1<<<BB*CC*HH/8, 256>>>(sre, sim);
        k_pass2<<<BB*CC*48, 256>>>(mask);
        k_pass3<<<BB*HH, 256>>>(sre, sim, lam);
        k_reduce<<<BB, 384>>>(0);               // alpha = rtr / pAp
        k_update_xr<<<BB*HH, 384>>>(out);       // x += a p; r -= a Ap; |r|^2 partials
        k_reduce<<<BB, 384>>>(2);               // beta = new/old; rtr = new
        k_update_p<<<BB*HH, 384>>>();           // p = r + beta p
    }
}

// round 3
// speedup vs baseline: 1.2747x; 1.2747x over previous
#include <cuda_runtime.h>

#define BB 4
#define CC 16
#define HH 384
#define WW 384
#define NPIX (HH*WW)
#define IMG  (BB*NPIX)
#define WSN  (BB*CC*NPIX)

// ---------------- device scratch ----------------
__device__ float2 g_ws[WSN];       // [B,C,H,Wstored] complex workspace (permuted W layout in CG loop)
__device__ float2 g_p [IMG];
__device__ float2 g_r [IMG];
__device__ float2 g_Ap[IMG];
__device__ float  g_part_rr [BB*HH];
__device__ float  g_part_pap[BB*HH];
__device__ float  g_rtr2[2*BB];    // ping-pong rTr per batch
__device__ float2 g_tw[384];       // e^{-2*pi*i*k/384}
__device__ float  g_maskp[BB*HH*WW]; // mask permuted to stored-W layout

// ---------------- complex helpers ----------------
__device__ __forceinline__ float2 cadd(float2 a, float2 b){ return make_float2(a.x+b.x, a.y+b.y); }
__device__ __forceinline__ float2 csub(float2 a, float2 b){ return make_float2(a.x-b.x, a.y-b.y); }
__device__ __forceinline__ float2 cmul(float2 a, float2 b){
    return make_float2(fmaf(a.x,b.x,-a.y*b.y), fmaf(a.x,b.y, a.y*b.x));
}
__device__ __forceinline__ float2 cneg(float2 a){ return make_float2(-a.x, -a.y); }
__device__ __forceinline__ int brev5(int lane){ return (int)(__brev((unsigned)lane) >> 27); }

__global__ void k_init_tw(){
    int k = threadIdx.x;
    float s, c;
    sincospif((float)k / 192.0f, &s, &c);
    g_tw[k] = make_float2(c, -s);
}

// natural w for stored column c: n = c/12 + 32*(c%12)
__global__ void k_init_maskp(const float* __restrict__ mask){
    int bh = blockIdx.x; int c = threadIdx.x;
    int w = (c / 12) + 32 * (c % 12);
    g_maskp[bh*WW + c] = mask[bh*WW + w];
}

template<bool INV>
__device__ __forceinline__ float2 twbase(int idx){
    float2 u = g_tw[idx];
    if (INV) u.y = -u.y;
    return u;
}

// W12^e = exp(-+ 2 pi i e / 12), hardcoded (folds to immediates under full unroll)
template<bool INV>
__device__ __forceinline__ float2 w12e(int e){
    const float C = 0.86602540378443864676f;
    const float re[12] = {1.f,C,.5f,0.f,-.5f,-C,-1.f,-C,-.5f,0.f,.5f,C};
    const float im[12] = {0.f,-.5f,-C,-1.f,-C,-.5f,0.f,.5f,C,1.f,C,.5f};
    return make_float2(re[e], INV ? -im[e] : im[e]);
}

// DFT-12 in place over index j -> m (unnormalized)
template<bool INV>
__device__ __forceinline__ void dft12(float2 z[12]){
    float2 Y[12];
    #pragma unroll
    for (int r = 0; r < 3; r++){
        float2 x0 = z[r], x1 = z[r+3], x2 = z[r+6], x3 = z[r+9];
        float2 t0 = cadd(x0,x2), t1 = csub(x0,x2);
        float2 t2 = cadd(x1,x3), t3 = csub(x1,x3);
        float2 jt3 = INV ? make_float2(-t3.y, t3.x) : make_float2(t3.y, -t3.x);
        Y[4*r+0] = cadd(t0,t2);
        Y[4*r+1] = cadd(t1,jt3);
        Y[4*r+2] = csub(t0,t2);
        Y[4*r+3] = csub(t1,jt3);
    }
    #pragma unroll
    for (int m = 0; m < 12; m++){
        int q = m & 3;
        float2 w1 = w12e<INV>(m % 12);
        float2 w2 = w12e<INV>((2*m) % 12);
        z[m] = cadd(Y[q], cadd(cmul(w1, Y[4+q]), cmul(w2, Y[8+q])));
    }
}

// 32-pt Gentleman-Sande DIF across lanes; T[st] = -u^{192/h} (h=16,8,4,2); last stage twiddle-free
__device__ __forceinline__ void gs32(float2 v[12], int lane, const float2 T[4]){
    #pragma unroll
    for (int st = 0; st < 5; st++){
        int h = 16 >> st;
        bool up = (lane & h) != 0;
        #pragma unroll
        for (int m = 0; m < 12; m++){
            float2 o;
            o.x = __shfl_xor_sync(0xffffffffu, v[m].x, h);
            o.y = __shfl_xor_sync(0xffffffffu, v[m].y, h);
            float2 s = up ? csub(o, v[m]) : cadd(v[m], o);
            v[m] = (up && st < 4) ? cmul(s, T[st]) : s;
        }
    }
}

// Variant A: input v[j] = x[lane + 32j] (natural); output lane holds X[12*brev5(lane)+m]
template<bool INV>
__device__ __forceinline__ void fftA(float2 v[12], int lane){
    dft12<INV>(v);
    float2 u  = twbase<INV>(lane);
    float2 p2 = cmul(u,u),  p3 = cmul(p2,u), p4 = cmul(p2,p2);
    float2 p5 = cmul(p4,u), p6 = cmul(p4,p2), p7 = cmul(p4,p3), p8 = cmul(p4,p4);
    float2 p9 = cmul(p8,u), p10= cmul(p8,p2), p11= cmul(p8,p3);
    v[1]=cmul(v[1],u);   v[2]=cmul(v[2],p2);  v[3]=cmul(v[3],p3);
    v[4]=cmul(v[4],p4);  v[5]=cmul(v[5],p5);  v[6]=cmul(v[6],p6);
    v[7]=cmul(v[7],p7);  v[8]=cmul(v[8],p8);  v[9]=cmul(v[9],p9);
    v[10]=cmul(v[10],p10); v[11]=cmul(v[11],p11);
    float2 u12 = cmul(p8,p4), u24 = cmul(u12,u12), u48 = cmul(u24,u24), u96 = cmul(u48,u48);
    float2 T[4] = { cneg(u12), cneg(u24), cneg(u48), cneg(u96) };
    gs32(v, lane, T);
}

// Variant B: input v[j] = x[12*lane + j] (natural); output lane holds X[32*m + brev5(lane)]
template<bool INV>
__device__ __forceinline__ void fftB(float2 v[12], int lane){
    float2 u  = twbase<INV>(lane);
    float2 u2 = cmul(u,u), u4 = cmul(u2,u2), u8 = cmul(u4,u4);
    float2 u12= cmul(u8,u4), u24 = cmul(u12,u12), u48 = cmul(u24,u24), u96 = cmul(u48,u48);
    float2 T[4] = { cneg(u12), cneg(u24), cneg(u48), cneg(u96) };
    gs32(v, lane, T);
    float2 w  = twbase<INV>(brev5(lane));
    float2 q2 = cmul(w,w),  q3 = cmul(q2,w), q4 = cmul(q2,q2);
    float2 q5 = cmul(q4,w), q6 = cmul(q4,q2), q7 = cmul(q4,q3), q8 = cmul(q4,q4);
    float2 q9 = cmul(q8,w), q10= cmul(q8,q2), q11= cmul(q8,q3);
    v[1]=cmul(v[1],w);   v[2]=cmul(v[2],q2);  v[3]=cmul(v[3],q3);
    v[4]=cmul(v[4],q4);  v[5]=cmul(v[5],q5);  v[6]=cmul(v[6],q6);
    v[7]=cmul(v[7],q7);  v[8]=cmul(v[8],q8);  v[9]=cmul(v[9],q9);
    v[10]=cmul(v[10],q10); v[11]=cmul(v[11],q11);
    dft12<INV>(v);
}

// block reduce, valid result in thread 0; safe to call repeatedly
__device__ __forceinline__ float block_reduce(float v, float* sred, int nwarp){
    int lane = threadIdx.x & 31, w = threadIdx.x >> 5;
    #pragma unroll
    for (int o = 16; o; o >>= 1) v += __shfl_down_sync(0xffffffffu, v, o);
    if (lane == 0) sred[w] = v;
    __syncthreads();
    v = 0.f;
    if (w == 0 && lane < nwarp) v = sred[lane];
    if (w == 0){
        #pragma unroll
        for (int o = 16; o; o >>= 1) v += __shfl_down_sync(0xffffffffu, v, o);
    }
    __syncthreads();
    return v;
}

// ---------------- pass1: ws(stored) = FFT_W( s * p ), variant B, fully vectorized ----------------
__global__ void __launch_bounds__(256) k_pass1(const float* __restrict__ sre,
                                               const float* __restrict__ sim){
    int wid = threadIdx.x >> 5, lane = threadIdx.x & 31;
    int rid = blockIdx.x * 8 + wid;           // [0, B*C*H)
    int h = rid % HH; int bc = rid / HH; int b = bc / CC;
    int base  = rid * WW;
    int pbase = (b * HH + h) * WW;
    float sr[12], si[12]; float2 pv[12];
    {
        const float4* ar = (const float4*)(sre + base + 12*lane);
        const float4* ai = (const float4*)(sim + base + 12*lane);
        const float4* pp = (const float4*)(g_p + pbase + 12*lane);
        #pragma unroll
        for (int k = 0; k < 3; k++){ ((float4*)sr)[k] = ar[k]; ((float4*)si)[k] = ai[k]; }
        #pragma unroll
        for (int k = 0; k < 6; k++){ ((float4*)pv)[k] = pp[k]; }
    }
    float2 v[12];
    #pragma unroll
    for (int j = 0; j < 12; j++) v[j] = cmul(pv[j], make_float2(sr[j], si[j]));
    fftB<false>(v, lane);
    int kb = 12 * brev5(lane);
    float4* dst = (float4*)(g_ws + base + kb);
    #pragma unroll
    for (int k = 0; k < 6; k++) dst[k] = make_float4(v[2*k].x, v[2*k].y, v[2*k+1].x, v[2*k+1].y);
}

// ---------------- pass2: per stored column: FFT_H -> mask -> IFFT_H (in-place) ----------------
__global__ void __launch_bounds__(256) k_pass2(){
    __shared__ float sR[384*9], sI[384*9];
    int tid = threadIdx.x;
    int blk = blockIdx.x;                     // [0, B*C*48)
    int w0 = (blk % 48) * 8;
    int bc = blk / 48; int b = bc / CC;
    int basebc = bc * NPIX;
    const float4* src = (const float4*)(g_ws + basebc);
    for (int idx = tid; idx < 384*4; idx += 256){
        int hr = idx >> 2, c2 = idx & 3;
        float4 val = src[hr*(WW/2) + (w0>>1) + c2];
        int c0 = c2*2;
        sR[hr*9 + c0  ] = val.x; sI[hr*9 + c0  ] = val.y;
        sR[hr*9 + c0+1] = val.z; sI[hr*9 + c0+1] = val.w;
    }
    __syncthreads();
    int wrp = tid >> 5, lane = tid & 31;      // warp wrp owns stored column w0+wrp
    float2 v[12];
    #pragma unroll
    for (int j = 0; j < 12; j++){
        int h = lane + 32*j;
        v[j] = make_float2(sR[h*9+wrp], sI[h*9+wrp]);
    }
    fftA<false>(v, lane);
    int kb = 12 * brev5(lane);
    #pragma unroll
    for (int m = 0; m < 12; m++){
        float mv = g_maskp[(b*HH + kb + m)*WW + w0 + wrp];
        v[m].x *= mv; v[m].y *= mv;
    }
    __syncwarp();
    #pragma unroll
    for (int m = 0; m < 12; m++){ sR[(kb+m)*9+wrp] = v[m].x; sI[(kb+m)*9+wrp] = v[m].y; }
    __syncwarp();
    #pragma unroll
    for (int j = 0; j < 12; j++){
        int h = lane + 32*j;
        v[j] = make_float2(sR[h*9+wrp], sI[h*9+wrp]);
    }
    fftA<true>(v, lane);
    __syncwarp();
    #pragma unroll
    for (int m = 0; m < 12; m++){ sR[(kb+m)*9+wrp] = v[m].x; sI[(kb+m)*9+wrp] = v[m].y; }
    __syncthreads();
    float4* dst = (float4*)(g_ws + basebc);
    for (int idx = tid; idx < 384*4; idx += 256){
        int hr = idx >> 2, c2 = idx & 3;
        int c0 = c2*2;
        dst[hr*(WW/2) + (w0>>1) + c2] =
            make_float4(sR[hr*9+c0], sI[hr*9+c0], sR[hr*9+c0+1], sI[hr*9+c0+1]);
    }
}

// ---------------- pass3: Ap = (1/HW)*sum_c conj(s)*IFFT_W(ws) + lam*p; pAp partial ----------------
__global__ void __launch_bounds__(256) k_pass3(const float* __restrict__ sre,
                                               const float* __restrict__ sim,
                                               const float* __restrict__ lam_p){
    __shared__ float aR[8*384], aI[8*384];
    __shared__ float sred[16];
    int tid = threadIdx.x, wrp = tid >> 5, lane = tid & 31;
    int bh = blockIdx.x;                      // [0, B*H)
    int b = bh / HH, h = bh % HH;
    int kb = 12 * brev5(lane);
    float2 acc[12];
    #pragma unroll
    for (int m = 0; m < 12; m++) acc[m] = make_float2(0.f, 0.f);
    #pragma unroll
    for (int ci = 0; ci < 2; ci++){
        int c = wrp + ci*8;
        int base = ((b*CC + c)*HH + h)*WW;
        float2 v[12];
        {
            const float4* src = (const float4*)(g_ws + base + 12*lane);
            #pragma unroll
            for (int k = 0; k < 6; k++){
                float4 t = src[k];
                v[2*k]   = make_float2(t.x, t.y);
                v[2*k+1] = make_float2(t.z, t.w);
            }
        }
        fftA<true>(v, lane);
        float sr[12], si[12];
        {
            const float4* ar = (const float4*)(sre + base + kb);
            const float4* ai = (const float4*)(sim + base + kb);
            #pragma unroll
            for (int k = 0; k < 3; k++){ ((float4*)sr)[k] = ar[k]; ((float4*)si)[k] = ai[k]; }
        }
        #pragma unroll
        for (int m = 0; m < 12; m++)
            acc[m] = cadd(acc[m], cmul(make_float2(sr[m], -si[m]), v[m]));
    }
    #pragma unroll
    for (int m = 0; m < 12; m++){ aR[wrp*384 + kb+m] = acc[m].x; aI[wrp*384 + kb+m] = acc[m].y; }
    __syncthreads();
    float lam = *lam_p;
    float pap = 0.f;
    const float sc = 1.0f / (384.0f * 384.0f);
    for (int t = tid; t < 384; t += 256){
        float ar = 0.f, ai = 0.f;
        #pragma unroll
        for (int wv = 0; wv < 8; wv++){ ar += aR[wv*384+t]; ai += aI[wv*384+t]; }
        int idx = bh*WW + t;
        float2 pv = g_p[idx];
        float2 ap = make_float2(fmaf(lam, pv.x, ar*sc), fmaf(lam, pv.y, ai*sc));
        g_Ap[idx] = ap;
        pap += pv.x*ap.x + pv.y*ap.y;
    }
    float tot = block_reduce(pap, sred, 8);
    if (tid == 0) g_part_pap[bh] = tot;
}

// ---------------- rhs pass 1: ws(natural) = IFFT_H( y * mask ) ----------------
__global__ void __launch_bounds__(256) k_rhs1(const float* __restrict__ yre,
                                              const float* __restrict__ yim,
                                              const float* __restrict__ mask){
    __shared__ float sR[384*9], sI[384*9];
    int tid = threadIdx.x;
    int blk = blockIdx.x;
    int w0 = (blk % 48) * 8;
    int bc = blk / 48; int b = bc / CC;
    int basebc = bc * NPIX;
    for (int idx = tid; idx < 384*8; idx += 256){
        int h = idx >> 3, cl = idx & 7;
        int g = basebc + h*WW + w0 + cl;
        float mv = mask[(b*HH + h)*WW + w0 + cl];
        sR[h*9+cl] = yre[g]*mv; sI[h*9+cl] = yim[g]*mv;
    }
    __syncthreads();
    int wrp = tid >> 5, lane = tid & 31;
    float2 v[12];
    #pragma unroll
    for (int j = 0; j < 12; j++){
        int h = lane + 32*j;
        v[j] = make_float2(sR[h*9+wrp], sI[h*9+wrp]);
    }
    fftA<true>(v, lane);
    int kb = 12 * brev5(lane);
    __syncwarp();
    #pragma unroll
    for (int m = 0; m < 12; m++){ sR[(kb+m)*9+wrp] = v[m].x; sI[(kb+m)*9+wrp] = v[m].y; }
    __syncthreads();
    for (int idx = tid; idx < 384*8; idx += 256){
        int h = idx >> 3, cl = idx & 7;
        g_ws[basebc + h*WW + w0 + cl] = make_float2(sR[h*9+cl], sI[h*9+cl]);
    }
}

// ---------------- rhs pass 2: rhs = (1/384)*sum_c conj(s)*IFFT_W(ws natural) + lam*x0 ----------------
__global__ void __launch_bounds__(256) k_rhs2(const float* __restrict__ sre,
                                              const float* __restrict__ sim,
                                              const float* __restrict__ xre,
                                              const float* __restrict__ xim,
                                              const float* __restrict__ lam_p,
                                              float2* __restrict__ out){
    __shared__ float aR[8*384], aI[8*384];
    __shared__ float sred[16];
    int tid = threadIdx.x, wrp = tid >> 5, lane = tid & 31;
    int bh = blockIdx.x;
    int b = bh / HH, h = bh % HH;
    int kb = 12 * brev5(lane);
    float2 acc[12];
    #pragma unroll
    for (int m = 0; m < 12; m++) acc[m] = make_float2(0.f, 0.f);
    #pragma unroll
    for (int ci = 0; ci < 2; ci++){
        int c = wrp + ci*8;
        int base = ((b*CC + c)*HH + h)*WW;
        float2 v[12];
        #pragma unroll
        for (int j = 0; j < 12; j++) v[j] = g_ws[base + lane + 32*j];
        fftA<true>(v, lane);
        #pragma unroll
        for (int m = 0; m < 12; m++){
            int w = kb + m;
            float2 sv = make_float2(sre[base+w], -sim[base+w]);
            acc[m] = cadd(acc[m], cmul(sv, v[m]));
        }
    }
    #pragma unroll
    for (int m = 0; m < 12; m++){ aR[wrp*384 + kb+m] = acc[m].x; aI[wrp*384 + kb+m] = acc[m].y; }
    __syncthreads();
    float lam = *lam_p;
    float rr = 0.f;
    const float sc = 1.0f / 384.0f;   // ortho ifft2 total = unnormalized-inverse / 384
    for (int t = tid; t < 384; t += 256){
        float ar = 0.f, ai = 0.f;
        #pragma unroll
        for (int wv = 0; wv < 8; wv++){ ar += aR[wv*384+t]; ai += aI[wv*384+t]; }
        int idx = bh*WW + t;
        float2 rhs = make_float2(fmaf(lam, xre[idx], ar*sc), fmaf(lam, xim[idx], ai*sc));
        g_r[idx] = rhs; g_p[idx] = rhs;
        out[idx] = make_float2(0.f, 0.f);
        rr += rhs.x*rhs.x + rhs.y*rhs.y;
    }
    float tot = block_reduce(rr, sred, 8);
    if (tid == 0) g_part_rr[bh] = tot;
}

// ---------------- init rTr[0] ----------------
__global__ void __launch_bounds__(384) k_reduce_init(){
    __shared__ float sred[16];
    int b = blockIdx.x;
    float v = g_part_rr[b*HH + threadIdx.x];
    float tot = block_reduce(v, sred, 12);
    if (threadIdx.x == 0) g_rtr2[b] = tot;   // slot 0
}

// ---------------- update x,r (alpha computed inline from pAp partials) ----------------
__global__ void __launch_bounds__(384) k_update_xr(float2* __restrict__ out, int cur){
    __shared__ float sred[16];
    __shared__ float s_alpha;
    int bh = blockIdx.x; int b = bh / HH;
    float v = g_part_pap[b*HH + threadIdx.x];
    float pap = block_reduce(v, sred, 12);
    if (threadIdx.x == 0) s_alpha = g_rtr2[cur*BB + b] / pap;
    __syncthreads();
    float a = s_alpha;
    int i = bh*WW + threadIdx.x;
    float2 p = g_p[i], ap = g_Ap[i], x = out[i], r = g_r[i];
    x.x = fmaf(a, p.x, x.x);   x.y = fmaf(a, p.y, x.y);
    r.x = fmaf(-a, ap.x, r.x); r.y = fmaf(-a, ap.y, r.y);
    out[i] = x; g_r[i] = r;
    float rr = fmaf(r.x, r.x, r.y*r.y);
    float tot = block_reduce(rr, sred, 12);
    if (threadIdx.x == 0) g_part_rr[bh] = tot;
}

// ---------------- update p (beta computed inline from |r|^2 partials) ----------------
__global__ void __launch_bounds__(384) k_update_p(int cur){
    __shared__ float sred[16];
    __shared__ float s_beta;
    int bh = blockIdx.x; int b = bh / HH, h = bh % HH;
    float v = g_part_rr[b*HH + threadIdx.x];
    float rtrNew = block_reduce(v, sred, 12);
    if (threadIdx.x == 0){
        s_beta = rtrNew / g_rtr2[cur*BB + b];
        if (h == 0) g_rtr2[(cur^1)*BB + b] = rtrNew;
    }
    __syncthreads();
    float be = s_beta;
    int i = bh*WW + threadIdx.x;
    float2 r = g_r[i], p = g_p[i];
    g_p[i] = make_float2(fmaf(be, p.x, r.x), fmaf(be, p.y, r.y));
}

// ---------------- launch ----------------
extern "C" void kernel_launch(void* const* d_in, const int* in_sizes, int n_in,
                              void* d_out, int out_size){
    (void)in_sizes; (void)n_in; (void)out_size;
    const float* lam  = (const float*)d_in[0];
    const float* xre  = (const float*)d_in[1];
    const float* xim  = (const float*)d_in[2];
    const float* yre  = (const float*)d_in[3];
    const float* yim  = (const float*)d_in[4];
    const float* sre  = (const float*)d_in[5];
    const float* sim  = (const float*)d_in[6];
    const float* mask = (const float*)d_in[7];
    float2* out = (float2*)d_out;

    k_init_tw<<<1, 384>>>();
    k_init_maskp<<<BB*HH, 384>>>(mask);
    k_rhs1<<<BB*CC*48, 256>>>(yre, yim, mask);
    k_rhs2<<<BB*HH, 256>>>(sre, sim, xre, xim, lam, out);
    k_reduce_init<<<BB, 384>>>();

    for (int it = 0; it < 10; it++){
        int cur = it & 1;
        k_pass1<<<BB*CC*HH/8, 256>>>(sre, sim);
        k_pass2<<<BB*CC*48, 256>>>();
        k_pass3<<<BB*HH, 256>>>(sre, sim, lam);
        k_update_xr<<<BB*HH, 384>>>(out, cur);
        k_update_p<<<BB*HH, 384>>>(cur);
    }
}

// round 4
// speedup vs baseline: 1.3155x; 1.0320x over previous
#include <cuda_runtime.h>

#define BB 4
#define CC 16
#define HH 384
#define WW 384
#define NPIX (HH*WW)
#define IMG  (BB*NPIX)
#define WSN  (BB*CC*NPIX)

// ---------------- device scratch ----------------
__device__ float2 g_ws[WSN];       // [B,C,H,Wstored] (permuted W layout inside CG loop; natural for rhs)
__device__ float2 g_p [IMG];
__device__ float2 g_r [IMG];
__device__ float2 g_Ap[IMG];
__device__ float  g_part_rr [BB*HH];
__device__ float  g_part_pap[BB*HH];
__device__ float  g_rtr2[2*BB];    // ping-pong rTr per batch
__device__ float2 g_tw[384];       // e^{-2*pi*i*k/384}
__device__ float  g_maskp[BB*HH*WW]; // mask permuted to stored-W layout

// ---------------- complex helpers ----------------
__device__ __forceinline__ float2 cadd(float2 a, float2 b){ return make_float2(a.x+b.x, a.y+b.y); }
__device__ __forceinline__ float2 csub(float2 a, float2 b){ return make_float2(a.x-b.x, a.y-b.y); }
__device__ __forceinline__ float2 cmul(float2 a, float2 b){
    return make_float2(fmaf(a.x,b.x,-a.y*b.y), fmaf(a.x,b.y, a.y*b.x));
}
__device__ __forceinline__ float2 cneg(float2 a){ return make_float2(-a.x, -a.y); }
__device__ __forceinline__ int brev5(int lane){ return (int)(__brev((unsigned)lane) >> 27); }

__global__ void k_init_tw(){
    int k = threadIdx.x;
    float s, c;
    sincospif((float)k / 192.0f, &s, &c);
    g_tw[k] = make_float2(c, -s);
}

// natural w for stored column c: n = c/12 + 32*(c%12)
__global__ void k_init_maskp(const float* __restrict__ mask){
    int bh = blockIdx.x; int c = threadIdx.x;
    int w = (c / 12) + 32 * (c % 12);
    g_maskp[bh*WW + c] = mask[bh*WW + w];
}

template<bool INV>
__device__ __forceinline__ float2 twbase(int idx){
    float2 u = g_tw[idx];
    if (INV) u.y = -u.y;
    return u;
}

// W12^e hardcoded (folds to immediates under full unroll)
template<bool INV>
__device__ __forceinline__ float2 w12e(int e){
    const float C = 0.86602540378443864676f;
    const float re[12] = {1.f,C,.5f,0.f,-.5f,-C,-1.f,-C,-.5f,0.f,.5f,C};
    const float im[12] = {0.f,-.5f,-C,-1.f,-C,-.5f,0.f,.5f,C,1.f,C,.5f};
    return make_float2(re[e], INV ? -im[e] : im[e]);
}

// DFT-12 in place over index j -> m (unnormalized)
template<bool INV>
__device__ __forceinline__ void dft12(float2 z[12]){
    float2 Y[12];
    #pragma unroll
    for (int r = 0; r < 3; r++){
        float2 x0 = z[r], x1 = z[r+3], x2 = z[r+6], x3 = z[r+9];
        float2 t0 = cadd(x0,x2), t1 = csub(x0,x2);
        float2 t2 = cadd(x1,x3), t3 = csub(x1,x3);
        float2 jt3 = INV ? make_float2(-t3.y, t3.x) : make_float2(t3.y, -t3.x);
        Y[4*r+0] = cadd(t0,t2);
        Y[4*r+1] = cadd(t1,jt3);
        Y[4*r+2] = csub(t0,t2);
        Y[4*r+3] = csub(t1,jt3);
    }
    #pragma unroll
    for (int m = 0; m < 12; m++){
        int q = m & 3;
        float2 w1 = w12e<INV>(m % 12);
        float2 w2 = w12e<INV>((2*m) % 12);
        z[m] = cadd(Y[q], cadd(cmul(w1, Y[4+q]), cmul(w2, Y[8+q])));
    }
}

// 32-pt GS DIF across lanes. REV=false: logical masks 16,8,4,2,1 on physical lanes.
// REV=true: logical index = brev5(physical lane); xor masks become 1,2,4,8,16.
template<bool REV>
__device__ __forceinline__ void gs32g(float2 v[12], int lane, const float2 T[4]){
    #pragma unroll
    for (int st = 0; st < 5; st++){
        int hp = REV ? (1 << st) : (16 >> st);
        bool up = (lane & hp) != 0;
        #pragma unroll
        for (int m = 0; m < 12; m++){
            float2 o;
            o.x = __shfl_xor_sync(0xffffffffu, v[m].x, hp);
            o.y = __shfl_xor_sync(0xffffffffu, v[m].y, hp);
            float2 s = up ? csub(o, v[m]) : cadd(v[m], o);
            v[m] = (up && st < 4) ? cmul(s, T[st]) : s;
        }
    }
}

// multiply v[1..11] by powers of w
__device__ __forceinline__ void twmul11(float2 v[12], float2 w){
    float2 p2 = cmul(w,w),  p3 = cmul(p2,w), p4 = cmul(p2,p2);
    float2 p5 = cmul(p4,w), p6 = cmul(p4,p2), p7 = cmul(p4,p3), p8 = cmul(p4,p4);
    float2 p9 = cmul(p8,w), p10= cmul(p8,p2), p11= cmul(p8,p3);
    v[1]=cmul(v[1],w);   v[2]=cmul(v[2],p2);  v[3]=cmul(v[3],p3);
    v[4]=cmul(v[4],p4);  v[5]=cmul(v[5],p5);  v[6]=cmul(v[6],p6);
    v[7]=cmul(v[7],p7);  v[8]=cmul(v[8],p8);  v[9]=cmul(v[9],p9);
    v[10]=cmul(v[10],p10); v[11]=cmul(v[11],p11);
}

__device__ __forceinline__ void makeT(float2 u, float2 T[4]){
    float2 u2 = cmul(u,u), u4 = cmul(u2,u2), u8 = cmul(u4,u4);
    float2 u12= cmul(u8,u4), u24 = cmul(u12,u12), u48 = cmul(u24,u24), u96 = cmul(u48,u48);
    T[0]=cneg(u12); T[1]=cneg(u24); T[2]=cneg(u48); T[3]=cneg(u96);
}

// Variant A: input v[j] = x[lane + 32j]; output: lane holds X[12*brev5(lane)+m]
template<bool INV>
__device__ __forceinline__ void fftA(float2 v[12], int lane){
    dft12<INV>(v);
    float2 u = twbase<INV>(lane);
    twmul11(v, u);
    float2 T[4]; makeT(u, T);
    gs32g<false>(v, lane, T);
}

// Variant B: input v[j] = x[12*lane + j]; output: lane holds X[32*m + brev5(lane)]
template<bool INV>
__device__ __forceinline__ void fftB(float2 v[12], int lane){
    float2 T[4]; makeT(twbase<INV>(lane), T);
    gs32g<false>(v, lane, T);
    twmul11(v, twbase<INV>(brev5(lane)));
    dft12<INV>(v);
}

// Variant Brev: input v[m] = x[12*brev5(lane)+m] (i.e. fftA's OUTPUT layout);
// output: lane holds X[lane + 32m] (natural).
template<bool INV>
__device__ __forceinline__ void fftBrev(float2 v[12], int lane){
    float2 T[4]; makeT(twbase<INV>(brev5(lane)), T);
    gs32g<true>(v, lane, T);
    twmul11(v, twbase<INV>(lane));
    dft12<INV>(v);
}

// block reduce, valid result in thread 0
__device__ __forceinline__ float block_reduce(float v, float* sred, int nwarp){
    int lane = threadIdx.x & 31, w = threadIdx.x >> 5;
    #pragma unroll
    for (int o = 16; o; o >>= 1) v += __shfl_down_sync(0xffffffffu, v, o);
    if (lane == 0) sred[w] = v;
    __syncthreads();
    v = 0.f;
    if (w == 0 && lane < nwarp) v = sred[lane];
    if (w == 0){
        #pragma unroll
        for (int o = 16; o; o >>= 1) v += __shfl_down_sync(0xffffffffu, v, o);
    }
    __syncthreads();
    return v;
}

// ---------------- pass1: ws(stored) = FFT_W( s * p ), variant B, vectorized ----------------
__global__ void __launch_bounds__(256) k_pass1(const float* __restrict__ sre,
                                               const float* __restrict__ sim){
    int wid = threadIdx.x >> 5, lane = threadIdx.x & 31;
    int rid = blockIdx.x * 8 + wid;           // [0, B*C*H)
    int h = rid % HH; int bc = rid / HH; int b = bc / CC;
    int base  = rid * WW;
    int pbase = (b * HH + h) * WW;
    float sr[12], si[12]; float2 pv[12];
    {
        const float4* ar = (const float4*)(sre + base + 12*lane);
        const float4* ai = (const float4*)(sim + base + 12*lane);
        const float4* pp = (const float4*)(g_p + pbase + 12*lane);
        #pragma unroll
        for (int k = 0; k < 3; k++){ ((float4*)sr)[k] = ar[k]; ((float4*)si)[k] = ai[k]; }
        #pragma unroll
        for (int k = 0; k < 6; k++){ ((float4*)pv)[k] = pp[k]; }
    }
    float2 v[12];
    #pragma unroll
    for (int j = 0; j < 12; j++) v[j] = cmul(pv[j], make_float2(sr[j], si[j]));
    fftB<false>(v, lane);
    int kb = 12 * brev5(lane);
    float4* dst = (float4*)(g_ws + base + kb);
    #pragma unroll
    for (int k = 0; k < 6; k++) dst[k] = make_float4(v[2*k].x, v[2*k].y, v[2*k+1].x, v[2*k+1].y);
}

// ---------------- pass2: stored column: FFT_H -> mask -> IFFT_H, single smem stage each side ----
__global__ void __launch_bounds__(256) k_pass2(){
    __shared__ float sR[384*9], sI[384*9];
    int tid = threadIdx.x;
    int blk = blockIdx.x;                     // [0, B*C*48)
    int w0 = (blk % 48) * 8;
    int bc = blk / 48; int b = bc / CC;
    int basebc = bc * NPIX;
    const float4* src = (const float4*)(g_ws + basebc);
    for (int idx = tid; idx < 384*4; idx += 256){
        int hr = idx >> 2, c2 = idx & 3;
        float4 val = src[hr*(WW/2) + (w0>>1) + c2];
        int c0 = c2*2;
        sR[hr*9 + c0  ] = val.x; sI[hr*9 + c0  ] = val.y;
        sR[hr*9 + c0+1] = val.z; sI[hr*9 + c0+1] = val.w;
    }
    __syncthreads();
    int wrp = tid >> 5, lane = tid & 31;      // warp wrp owns stored column w0+wrp
    float2 v[12];
    #pragma unroll
    for (int j = 0; j < 12; j++){
        int h = lane + 32*j;
        v[j] = make_float2(sR[h*9+wrp], sI[h*9+wrp]);
    }
    fftA<false>(v, lane);                     // lane holds H-freq kb+m
    int kb = 12 * brev5(lane);
    #pragma unroll
    for (int m = 0; m < 12; m++){
        float mv = g_maskp[(b*HH + kb + m)*WW + w0 + wrp];
        v[m].x *= mv; v[m].y *= mv;
    }
    fftBrev<true>(v, lane);                   // direct register-layout inverse; output natural
    __syncthreads();                          // everyone done reading sR/sI from stage 1
    #pragma unroll
    for (int m = 0; m < 12; m++){
        int h = lane + 32*m;
        sR[h*9+wrp] = v[m].x; sI[h*9+wrp] = v[m].y;
    }
    __syncthreads();
    float4* dst = (float4*)(g_ws + basebc);
    for (int idx = tid; idx < 384*4; idx += 256){
        int hr = idx >> 2, c2 = idx & 3;
        int c0 = c2*2;
        dst[hr*(WW/2) + (w0>>1) + c2] =
            make_float4(sR[hr*9+c0], sI[hr*9+c0], sR[hr*9+c0+1], sI[hr*9+c0+1]);
    }
}

// ---------------- pass3: warp-per-row, register coil accumulation ----------------
__global__ void __launch_bounds__(128) k_pass3(const float* __restrict__ sre,
                                               const float* __restrict__ sim,
                                               const float* __restrict__ lam_p){
    int w = threadIdx.x >> 5, lane = threadIdx.x & 31;
    int bh = blockIdx.x * 4 + w;              // [0, B*H)
    int b = bh / HH, h = bh % HH;
    int kb = 12 * brev5(lane);
    float2 acc[12];
    #pragma unroll
    for (int m = 0; m < 12; m++) acc[m] = make_float2(0.f, 0.f);
    int base0 = (b*CC*HH + h)*WW;
    #pragma unroll 1
    for (int c = 0; c < CC; c++){
        int base = base0 + c*HH*WW;
        float2 v[12];
        {
            const float4* src = (const float4*)(g_ws + base + 12*lane);
            #pragma unroll
            for (int k = 0; k < 6; k++){
                float4 t = src[k];
                v[2*k]   = make_float2(t.x, t.y);
                v[2*k+1] = make_float2(t.z, t.w);
            }
        }
        fftA<true>(v, lane);
        float sr[12], si[12];
        {
            const float4* ar = (const float4*)(sre + base + kb);
            const float4* ai = (const float4*)(sim + base + kb);
            #pragma unroll
            for (int k = 0; k < 3; k++){ ((float4*)sr)[k] = ar[k]; ((float4*)si)[k] = ai[k]; }
        }
        #pragma unroll
        for (int m = 0; m < 12; m++)
            acc[m] = cadd(acc[m], cmul(make_float2(sr[m], -si[m]), v[m]));
    }
    float lam = *lam_p;
    const float sc = 1.0f / (384.0f * 384.0f);
    int idx = bh*WW + kb;
    float2 pv[12];
    {
        const float4* pp = (const float4*)(g_p + idx);
        #pragma unroll
        for (int k = 0; k < 6; k++){
            float4 t = pp[k];
            pv[2*k]   = make_float2(t.x, t.y);
            pv[2*k+1] = make_float2(t.z, t.w);
        }
    }
    float pap = 0.f;
    float4* dst = (float4*)(g_Ap + idx);
    #pragma unroll
    for (int k = 0; k < 6; k++){
        float2 a0 = make_float2(fmaf(lam, pv[2*k].x,   acc[2*k].x*sc),
                                fmaf(lam, pv[2*k].y,   acc[2*k].y*sc));
        float2 a1 = make_float2(fmaf(lam, pv[2*k+1].x, acc[2*k+1].x*sc),
                                fmaf(lam, pv[2*k+1].y, acc[2*k+1].y*sc));
        dst[k] = make_float4(a0.x, a0.y, a1.x, a1.y);
        pap += pv[2*k].x*a0.x + pv[2*k].y*a0.y + pv[2*k+1].x*a1.x + pv[2*k+1].y*a1.y;
    }
    #pragma unroll
    for (int o = 16; o; o >>= 1) pap += __shfl_down_sync(0xffffffffu, pap, o);
    if (lane == 0) g_part_pap[bh] = pap;
}

// ---------------- rhs pass 1: ws(natural) = IFFT_H( y * mask ) ----------------
__global__ void __launch_bounds__(256) k_rhs1(const float* __restrict__ yre,
                                              const float* __restrict__ yim,
                                              const float* __restrict__ mask){
    __shared__ float sR[384*9], sI[384*9];
    int tid = threadIdx.x;
    int blk = blockIdx.x;
    int w0 = (blk % 48) * 8;
    int bc = blk / 48; int b = bc / CC;
    int basebc = bc * NPIX;
    for (int idx = tid; idx < 384*8; idx += 256){
        int h = idx >> 3, cl = idx & 7;
        int g = basebc + h*WW + w0 + cl;
        float mv = mask[(b*HH + h)*WW + w0 + cl];
        sR[h*9+cl] = yre[g]*mv; sI[h*9+cl] = yim[g]*mv;
    }
    __syncthreads();
    int wrp = tid >> 5, lane = tid & 31;
    float2 v[12];
    #pragma unroll
    for (int j = 0; j < 12; j++){
        int h = lane + 32*j;
        v[j] = make_float2(sR[h*9+wrp], sI[h*9+wrp]);
    }
    fftA<true>(v, lane);
    int kb = 12 * brev5(lane);
    __syncthreads();
    #pragma unroll
    for (int m = 0; m < 12; m++){ sR[(kb+m)*9+wrp] = v[m].x; sI[(kb+m)*9+wrp] = v[m].y; }
    __syncthreads();
    for (int idx = tid; idx < 384*8; idx += 256){
        int h = idx >> 3, cl = idx & 7;
        g_ws[basebc + h*WW + w0 + cl] = make_float2(sR[h*9+cl], sI[h*9+cl]);
    }
}

// ---------------- rhs pass 2: warp-per-row; rhs = (1/384)*sum_c conj(s)*IFFT_W(ws natural) + lam*x0
__global__ void __launch_bounds__(128) k_rhs2(const float* __restrict__ sre,
                                              const float* __restrict__ sim,
                                              const float* __restrict__ xre,
                                              const float* __restrict__ xim,
                                              const float* __restrict__ lam_p,
                                              float2* __restrict__ out){
    int w = threadIdx.x >> 5, lane = threadIdx.x & 31;
    int bh = blockIdx.x * 4 + w;
    int b = bh / HH, h = bh % HH;
    int kb = 12 * brev5(lane);
    float2 acc[12];
    #pragma unroll
    for (int m = 0; m < 12; m++) acc[m] = make_float2(0.f, 0.f);
    int base0 = (b*CC*HH + h)*WW;
    #pragma unroll 1
    for (int c = 0; c < CC; c++){
        int base = base0 + c*HH*WW;
        float2 v[12];
        #pragma unroll
        for (int j = 0; j < 12; j++) v[j] = g_ws[base + lane + 32*j];
        fftA<true>(v, lane);
        float sr[12], si[12];
        {
            const float4* ar = (const float4*)(sre + base + kb);
            const float4* ai = (const float4*)(sim + base + kb);
            #pragma unroll
            for (int k = 0; k < 3; k++){ ((float4*)sr)[k] = ar[k]; ((float4*)si)[k] = ai[k]; }
        }
        #pragma unroll
        for (int m = 0; m < 12; m++)
            acc[m] = cadd(acc[m], cmul(make_float2(sr[m], -si[m]), v[m]));
    }
    float lam = *lam_p;
    const float sc = 1.0f / 384.0f;   // ortho ifft2 total = unnormalized-inverse / 384
    int idx = bh*WW + kb;
    float xr[12], xi[12];
    {
        const float4* axr = (const float4*)(xre + idx);
        const float4* axi = (const float4*)(xim + idx);
        #pragma unroll
        for (int k = 0; k < 3; k++){ ((float4*)xr)[k] = axr[k]; ((float4*)xi)[k] = axi[k]; }
    }
    float rr = 0.f;
    float4* dr = (float4*)(g_r + idx);
    float4* dp = (float4*)(g_p + idx);
    float4* doz= (float4*)(out + idx);
    #pragma unroll
    for (int k = 0; k < 6; k++){
        float2 r0 = make_float2(fmaf(lam, xr[2*k],   acc[2*k].x*sc),
                                fmaf(lam, xi[2*k],   acc[2*k].y*sc));
        float2 r1 = make_float2(fmaf(lam, xr[2*k+1], acc[2*k+1].x*sc),
                                fmaf(lam, xi[2*k+1], acc[2*k+1].y*sc));
        float4 pack = make_float4(r0.x, r0.y, r1.x, r1.y);
        dr[k] = pack; dp[k] = pack;
        doz[k] = make_float4(0.f, 0.f, 0.f, 0.f);
        rr += r0.x*r0.x + r0.y*r0.y + r1.x*r1.x + r1.y*r1.y;
    }
    #pragma unroll
    for (int o = 16; o; o >>= 1) rr += __shfl_down_sync(0xffffffffu, rr, o);
    if (lane == 0) g_part_rr[bh] = rr;
}

// ---------------- init rTr[0] ----------------
__global__ void __launch_bounds__(384) k_reduce_init(){
    __shared__ float sred[16];
    int b = blockIdx.x;
    float v = g_part_rr[b*HH + threadIdx.x];
    float tot = block_reduce(v, sred, 12);
    if (threadIdx.x == 0) g_rtr2[b] = tot;   // slot 0
}

// ---------------- update x,r ----------------
__global__ void __launch_bounds__(384) k_update_xr(float2* __restrict__ out, int cur){
    __shared__ float sred[16];
    __shared__ float s_alpha;
    int bh = blockIdx.x; int b = bh / HH;
    float v = g_part_pap[b*HH + threadIdx.x];
    float pap = block_reduce(v, sred, 12);
    if (threadIdx.x == 0) s_alpha = g_rtr2[cur*BB + b] / pap;
    __syncthreads();
    float a = s_alpha;
    int i = bh*WW + threadIdx.x;
    float2 p = g_p[i], ap = g_Ap[i], x = out[i], r = g_r[i];
    x.x = fmaf(a, p.x, x.x);   x.y = fmaf(a, p.y, x.y);
    r.x = fmaf(-a, ap.x, r.x); r.y = fmaf(-a, ap.y, r.y);
    out[i] = x; g_r[i] = r;
    float rr = fmaf(r.x, r.x, r.y*r.y);
    float tot = block_reduce(rr, sred, 12);
    if (threadIdx.x == 0) g_part_rr[bh] = tot;
}

// ---------------- update p ----------------
__global__ void __launch_bounds__(384) k_update_p(int cur){
    __shared__ float sred[16];
    __shared__ float s_beta;
    int bh = blockIdx.x; int b = bh / HH, h = bh % HH;
    float v = g_part_rr[b*HH + threadIdx.x];
    float rtrNew = block_reduce(v, sred, 12);
    if (threadIdx.x == 0){
        s_beta = rtrNew / g_rtr2[cur*BB + b];
        if (h == 0) g_rtr2[(cur^1)*BB + b] = rtrNew;
    }
    __syncthreads();
    float be = s_beta;
    int i = bh*WW + threadIdx.x;
    float2 r = g_r[i], p = g_p[i];
    g_p[i] = make_float2(fmaf(be, p.x, r.x), fmaf(be, p.y, r.y));
}

// ---------------- launch ----------------
extern "C" void kernel_launch(void* const* d_in, const int* in_sizes, int n_in,
                              void* d_out, int out_size){
    (void)in_sizes; (void)n_in; (void)out_size;
    const float* lam  = (const float*)d_in[0];
    const float* xre  = (const float*)d_in[1];
    const float* xim  = (const float*)d_in[2];
    const float* yre  = (const float*)d_in[3];
    const float* yim  = (const float*)d_in[4];
    const float* sre  = (const float*)d_in[5];
    const float* sim  = (const float*)d_in[6];
    const float* mask = (const float*)d_in[7];
    float2* out = (float2*)d_out;

    k_init_tw<<<1, 384>>>();
    k_init_maskp<<<BB*HH, 384>>>(mask);
    k_rhs1<<<BB*CC*48, 256>>>(yre, yim, mask);
    k_rhs2<<<BB*HH/4, 128>>>(sre, sim, xre, xim, lam, out);
    k_reduce_init<<<BB, 384>>>();

    for (int it = 0; it < 10; it++){
        int cur = it & 1;
        k_pass1<<<BB*CC*HH/8, 256>>>(sre, sim);
        k_pass2<<<BB*CC*48, 256>>>();
        k_pass3<<<BB*HH/4, 128>>>(sre, sim, lam);
        k_update_xr<<<BB*HH, 384>>>(out, cur);
        k_update_p<<<BB*HH, 384>>>(cur);
    }
}

// round 5
// speedup vs baseline: 1.4143x; 1.0751x over previous
#include <cuda_runtime.h>

#define BB 4
#define CC 16
#define HH 384
#define WW 384
#define NPIX (HH*WW)
#define IMG  (BB*NPIX)
#define WSN  (BB*CC*NPIX)

// ---------------- device scratch ----------------
__device__ float2 g_ws[WSN];       // [B,C,H,Wstored] (permuted W layout inside CG loop; natural for rhs)
__device__ float2 g_p [IMG];
__device__ float2 g_r [IMG];
__device__ float2 g_Ap[IMG];
__device__ float  g_part_rr [BB*HH];
__device__ float  g_part_pap[BB*HH];
__device__ float  g_rtr2[2*BB];    // ping-pong rTr per batch
__device__ float2 g_tw[384];       // e^{-2*pi*i*k/384}
__device__ float  g_maskp[BB*HH*WW]; // mask permuted to stored-W layout

// ---------------- complex helpers ----------------
__device__ __forceinline__ float2 cadd(float2 a, float2 b){ return make_float2(a.x+b.x, a.y+b.y); }
__device__ __forceinline__ float2 csub(float2 a, float2 b){ return make_float2(a.x-b.x, a.y-b.y); }
__device__ __forceinline__ float2 cmul(float2 a, float2 b){
    return make_float2(fmaf(a.x,b.x,-a.y*b.y), fmaf(a.x,b.y, a.y*b.x));
}
__device__ __forceinline__ float2 cneg(float2 a){ return make_float2(-a.x, -a.y); }
__device__ __forceinline__ int brev5(int lane){ return (int)(__brev((unsigned)lane) >> 27); }

__global__ void k_init_tw(){
    int k = threadIdx.x;
    float s, c;
    sincospif((float)k / 192.0f, &s, &c);
    g_tw[k] = make_float2(c, -s);
}

// natural w for stored column c: n = c/12 + 32*(c%12)
__global__ void k_init_maskp(const float* __restrict__ mask){
    int bh = blockIdx.x; int c = threadIdx.x;
    int w = (c / 12) + 32 * (c % 12);
    g_maskp[bh*WW + c] = mask[bh*WW + w];
}

template<bool INV>
__device__ __forceinline__ float2 twbase(int idx){
    float2 u = g_tw[idx];
    if (INV) u.y = -u.y;
    return u;
}

// W12^e hardcoded (folds to immediates under full unroll)
template<bool INV>
__device__ __forceinline__ float2 w12e(int e){
    const float C = 0.86602540378443864676f;
    const float re[12] = {1.f,C,.5f,0.f,-.5f,-C,-1.f,-C,-.5f,0.f,.5f,C};
    const float im[12] = {0.f,-.5f,-C,-1.f,-C,-.5f,0.f,.5f,C,1.f,C,.5f};
    return make_float2(re[e], INV ? -im[e] : im[e]);
}

// DFT-12 in place over index j -> m (unnormalized)
template<bool INV>
__device__ __forceinline__ void dft12(float2 z[12]){
    float2 Y[12];
    #pragma unroll
    for (int r = 0; r < 3; r++){
        float2 x0 = z[r], x1 = z[r+3], x2 = z[r+6], x3 = z[r+9];
        float2 t0 = cadd(x0,x2), t1 = csub(x0,x2);
        float2 t2 = cadd(x1,x3), t3 = csub(x1,x3);
        float2 jt3 = INV ? make_float2(-t3.y, t3.x) : make_float2(t3.y, -t3.x);
        Y[4*r+0] = cadd(t0,t2);
        Y[4*r+1] = cadd(t1,jt3);
        Y[4*r+2] = csub(t0,t2);
        Y[4*r+3] = csub(t1,jt3);
    }
    #pragma unroll
    for (int m = 0; m < 12; m++){
        int q = m & 3;
        float2 w1 = w12e<INV>(m % 12);
        float2 w2 = w12e<INV>((2*m) % 12);
        z[m] = cadd(Y[q], cadd(cmul(w1, Y[4+q]), cmul(w2, Y[8+q])));
    }
}

// 32-pt GS DIF across lanes. REV=false: masks 16,8,4,2,1; REV=true: 1,2,4,8,16.
template<bool REV>
__device__ __forceinline__ void gs32g(float2 v[12], int lane, const float2 T[4]){
    #pragma unroll
    for (int st = 0; st < 5; st++){
        int hp = REV ? (1 << st) : (16 >> st);
        bool up = (lane & hp) != 0;
        #pragma unroll
        for (int m = 0; m < 12; m++){
            float2 o;
            o.x = __shfl_xor_sync(0xffffffffu, v[m].x, hp);
            o.y = __shfl_xor_sync(0xffffffffu, v[m].y, hp);
            float2 s = up ? csub(o, v[m]) : cadd(v[m], o);
            v[m] = (up && st < 4) ? cmul(s, T[st]) : s;
        }
    }
}

// multiply v[1..11] by powers of w
__device__ __forceinline__ void twmul11(float2 v[12], float2 w){
    float2 p2 = cmul(w,w),  p3 = cmul(p2,w), p4 = cmul(p2,p2);
    float2 p5 = cmul(p4,w), p6 = cmul(p4,p2), p7 = cmul(p4,p3), p8 = cmul(p4,p4);
    float2 p9 = cmul(p8,w), p10= cmul(p8,p2), p11= cmul(p8,p3);
    v[1]=cmul(v[1],w);   v[2]=cmul(v[2],p2);  v[3]=cmul(v[3],p3);
    v[4]=cmul(v[4],p4);  v[5]=cmul(v[5],p5);  v[6]=cmul(v[6],p6);
    v[7]=cmul(v[7],p7);  v[8]=cmul(v[8],p8);  v[9]=cmul(v[9],p9);
    v[10]=cmul(v[10],p10); v[11]=cmul(v[11],p11);
}

__device__ __forceinline__ void makeT(float2 u, float2 T[4]){
    float2 u2 = cmul(u,u), u4 = cmul(u2,u2), u8 = cmul(u4,u4);
    float2 u12= cmul(u8,u4), u24 = cmul(u12,u12), u48 = cmul(u24,u24), u96 = cmul(u48,u48);
    T[0]=cneg(u12); T[1]=cneg(u24); T[2]=cneg(u48); T[3]=cneg(u96);
}

// Variant A: input v[j] = x[lane + 32j]; output: lane holds X[12*brev5(lane)+m]
template<bool INV>
__device__ __forceinline__ void fftA(float2 v[12], int lane){
    dft12<INV>(v);
    float2 u = twbase<INV>(lane);
    twmul11(v, u);
    float2 T[4]; makeT(u, T);
    gs32g<false>(v, lane, T);
}

// Variant B: input v[j] = x[12*lane + j]; output: lane holds X[32*m + brev5(lane)]
template<bool INV>
__device__ __forceinline__ void fftB(float2 v[12], int lane){
    float2 T[4]; makeT(twbase<INV>(lane), T);
    gs32g<false>(v, lane, T);
    twmul11(v, twbase<INV>(brev5(lane)));
    dft12<INV>(v);
}

// Variant Brev: input v[m] = x[12*brev5(lane)+m] (fftA's OUTPUT layout); output natural.
template<bool INV>
__device__ __forceinline__ void fftBrev(float2 v[12], int lane){
    float2 T[4]; makeT(twbase<INV>(brev5(lane)), T);
    gs32g<true>(v, lane, T);
    twmul11(v, twbase<INV>(lane));
    dft12<INV>(v);
}

// block reduce, valid result in thread 0
__device__ __forceinline__ float block_reduce(float v, float* sred, int nwarp){
    int lane = threadIdx.x & 31, w = threadIdx.x >> 5;
    #pragma unroll
    for (int o = 16; o; o >>= 1) v += __shfl_down_sync(0xffffffffu, v, o);
    if (lane == 0) sred[w] = v;
    __syncthreads();
    v = 0.f;
    if (w == 0 && lane < nwarp) v = sred[lane];
    if (w == 0){
        #pragma unroll
        for (int o = 16; o; o >>= 1) v += __shfl_down_sync(0xffffffffu, v, o);
    }
    __syncthreads();
    return v;
}

// ---------------- pass1: ws(stored) = FFT_W( s * p ), variant B, vectorized ----------------
__global__ void __launch_bounds__(256) k_pass1(const float* __restrict__ sre,
                                               const float* __restrict__ sim){
    int wid = threadIdx.x >> 5, lane = threadIdx.x & 31;
    int rid = blockIdx.x * 8 + wid;           // [0, B*C*H)
    int h = rid % HH; int bc = rid / HH; int b = bc / CC;
    int base  = rid * WW;
    int pbase = (b * HH + h) * WW;
    float sr[12], si[12]; float2 pv[12];
    {
        const float4* ar = (const float4*)(sre + base + 12*lane);
        const float4* ai = (const float4*)(sim + base + 12*lane);
        const float4* pp = (const float4*)(g_p + pbase + 12*lane);
        #pragma unroll
        for (int k = 0; k < 3; k++){ ((float4*)sr)[k] = __ldcs(ar+k); ((float4*)si)[k] = __ldcs(ai+k); }
        #pragma unroll
        for (int k = 0; k < 6; k++){ ((float4*)pv)[k] = pp[k]; }
    }
    float2 v[12];
    #pragma unroll
    for (int j = 0; j < 12; j++) v[j] = cmul(pv[j], make_float2(sr[j], si[j]));
    fftB<false>(v, lane);
    int kb = 12 * brev5(lane);
    float4* dst = (float4*)(g_ws + base + kb);
    #pragma unroll
    for (int k = 0; k < 6; k++) dst[k] = make_float4(v[2*k].x, v[2*k].y, v[2*k+1].x, v[2*k+1].y);
}

// ---------------- pass2: stored column: FFT_H -> mask -> IFFT_H, registers in the middle ----
__global__ void __launch_bounds__(256) k_pass2(){
    __shared__ float sR[384*9], sI[384*9];
    int tid = threadIdx.x;
    int blk = blockIdx.x;                     // [0, B*C*48)
    int w0 = (blk % 48) * 8;
    int bc = blk / 48; int b = bc / CC;
    int basebc = bc * NPIX;
    const float4* src = (const float4*)(g_ws + basebc);
    for (int idx = tid; idx < 384*4; idx += 256){
        int hr = idx >> 2, c2 = idx & 3;
        float4 val = src[hr*(WW/2) + (w0>>1) + c2];
        int c0 = c2*2;
        sR[hr*9 + c0  ] = val.x; sI[hr*9 + c0  ] = val.y;
        sR[hr*9 + c0+1] = val.z; sI[hr*9 + c0+1] = val.w;
    }
    __syncthreads();
    int wrp = tid >> 5, lane = tid & 31;      // warp wrp owns stored column w0+wrp
    float2 v[12];
    #pragma unroll
    for (int j = 0; j < 12; j++){
        int h = lane + 32*j;
        v[j] = make_float2(sR[h*9+wrp], sI[h*9+wrp]);
    }
    fftA<false>(v, lane);                     // lane holds H-freq kb+m
    int kb = 12 * brev5(lane);
    #pragma unroll
    for (int m = 0; m < 12; m++){
        float mv = g_maskp[(b*HH + kb + m)*WW + w0 + wrp];
        v[m].x *= mv; v[m].y *= mv;
    }
    fftBrev<true>(v, lane);                   // register-layout inverse; output natural
    __syncthreads();
    #pragma unroll
    for (int m = 0; m < 12; m++){
        int h = lane + 32*m;
        sR[h*9+wrp] = v[m].x; sI[h*9+wrp] = v[m].y;
    }
    __syncthreads();
    float4* dst = (float4*)(g_ws + basebc);
    for (int idx = tid; idx < 384*4; idx += 256){
        int hr = idx >> 2, c2 = idx & 3;
        int c0 = c2*2;
        dst[hr*(WW/2) + (w0>>1) + c2] =
            make_float4(sR[hr*9+c0], sI[hr*9+c0], sR[hr*9+c0+1], sI[hr*9+c0+1]);
    }
}

// ---------------- pass3: block-per-row, 4 warps x 4 coils, smem combine ----------------
__global__ void __launch_bounds__(128) k_pass3(const float* __restrict__ sre,
                                               const float* __restrict__ sim,
                                               const float* __restrict__ lam_p){
    __shared__ float aR[4*384], aI[4*384];
    __shared__ float sred[8];
    int wrp = threadIdx.x >> 5, lane = threadIdx.x & 31;
    int bh = blockIdx.x;                      // [0, B*H)
    int b = bh / HH, h = bh % HH;
    int kb = 12 * brev5(lane);
    float2 acc[12];
    #pragma unroll
    for (int m = 0; m < 12; m++) acc[m] = make_float2(0.f, 0.f);
    int base0 = (b*CC*HH + h)*WW;
    #pragma unroll 1
    for (int ci = 0; ci < 4; ci++){
        int c = wrp + 4*ci;
        int base = base0 + c*HH*WW;
        float2 v[12];
        {
            const float4* src = (const float4*)(g_ws + base + 12*lane);
            #pragma unroll
            for (int k = 0; k < 6; k++){
                float4 t = src[k];
                v[2*k]   = make_float2(t.x, t.y);
                v[2*k+1] = make_float2(t.z, t.w);
            }
        }
        fftA<true>(v, lane);
        float sr[12], si[12];
        {
            const float4* ar = (const float4*)(sre + base + kb);
            const float4* ai = (const float4*)(sim + base + kb);
            #pragma unroll
            for (int k = 0; k < 3; k++){ ((float4*)sr)[k] = __ldcs(ar+k); ((float4*)si)[k] = __ldcs(ai+k); }
        }
        #pragma unroll
        for (int m = 0; m < 12; m++)
            acc[m] = cadd(acc[m], cmul(make_float2(sr[m], -si[m]), v[m]));
    }
    #pragma unroll
    for (int m = 0; m < 12; m++){ aR[wrp*384 + kb+m] = acc[m].x; aI[wrp*384 + kb+m] = acc[m].y; }
    __syncthreads();
    float lam = *lam_p;
    const float sc = 1.0f / (384.0f * 384.0f);
    float pap = 0.f;
    int t = threadIdx.x;
    #pragma unroll
    for (int e = 3*t; e < 3*t+3; e++){
        float ar = aR[e] + aR[384+e] + aR[768+e] + aR[1152+e];
        float ai = aI[e] + aI[384+e] + aI[768+e] + aI[1152+e];
        int idx = bh*WW + e;
        float2 pv = g_p[idx];
        float2 ap = make_float2(fmaf(lam, pv.x, ar*sc), fmaf(lam, pv.y, ai*sc));
        g_Ap[idx] = ap;
        pap += pv.x*ap.x + pv.y*ap.y;
    }
    float tot = block_reduce(pap, sred, 4);
    if (t == 0) g_part_pap[bh] = tot;
}

// ---------------- rhs pass 1: ws(natural) = IFFT_H( y * mask ) ----------------
__global__ void __launch_bounds__(256) k_rhs1(const float* __restrict__ yre,
                                              const float* __restrict__ yim,
                                              const float* __restrict__ mask){
    __shared__ float sR[384*9], sI[384*9];
    int tid = threadIdx.x;
    int blk = blockIdx.x;
    int w0 = (blk % 48) * 8;
    int bc = blk / 48; int b = bc / CC;
    int basebc = bc * NPIX;
    for (int idx = tid; idx < 384*8; idx += 256){
        int h = idx >> 3, cl = idx & 7;
        int g = basebc + h*WW + w0 + cl;
        float mv = mask[(b*HH + h)*WW + w0 + cl];
        sR[h*9+cl] = __ldcs(yre+g)*mv; sI[h*9+cl] = __ldcs(yim+g)*mv;
    }
    __syncthreads();
    int wrp = tid >> 5, lane = tid & 31;
    float2 v[12];
    #pragma unroll
    for (int j = 0; j < 12; j++){
        int h = lane + 32*j;
        v[j] = make_float2(sR[h*9+wrp], sI[h*9+wrp]);
    }
    fftA<true>(v, lane);
    int kb = 12 * brev5(lane);
    __syncthreads();
    #pragma unroll
    for (int m = 0; m < 12; m++){ sR[(kb+m)*9+wrp] = v[m].x; sI[(kb+m)*9+wrp] = v[m].y; }
    __syncthreads();
    for (int idx = tid; idx < 384*8; idx += 256){
        int h = idx >> 3, cl = idx & 7;
        g_ws[basebc + h*WW + w0 + cl] = make_float2(sR[h*9+cl], sI[h*9+cl]);
    }
}

// ---------------- rhs pass 2: block-per-row, 4 warps x 4 coils; ws in natural layout ----------
__global__ void __launch_bounds__(128) k_rhs2(const float* __restrict__ sre,
                                              const float* __restrict__ sim,
                                              const float* __restrict__ xre,
                                              const float* __restrict__ xim,
                                              const float* __restrict__ lam_p,
                                              float2* __restrict__ out){
    __shared__ float aR[4*384], aI[4*384];
    __shared__ float sred[8];
    int wrp = threadIdx.x >> 5, lane = threadIdx.x & 31;
    int bh = blockIdx.x;
    int b = bh / HH, h = bh % HH;
    int kb = 12 * brev5(lane);
    float2 acc[12];
    #pragma unroll
    for (int m = 0; m < 12; m++) acc[m] = make_float2(0.f, 0.f);
    int base0 = (b*CC*HH + h)*WW;
    #pragma unroll 1
    for (int ci = 0; ci < 4; ci++){
        int c = wrp + 4*ci;
        int base = base0 + c*HH*WW;
        float2 v[12];
        #pragma unroll
        for (int j = 0; j < 12; j++) v[j] = g_ws[base + lane + 32*j];
        fftA<true>(v, lane);
        float sr[12], si[12];
        {
            const float4* ar = (const float4*)(sre + base + kb);
            const float4* ai = (const float4*)(sim + base + kb);
            #pragma unroll
            for (int k = 0; k < 3; k++){ ((float4*)sr)[k] = __ldcs(ar+k); ((float4*)si)[k] = __ldcs(ai+k); }
        }
        #pragma unroll
        for (int m = 0; m < 12; m++)
            acc[m] = cadd(acc[m], cmul(make_float2(sr[m], -si[m]), v[m]));
    }
    #pragma unroll
    for (int m = 0; m < 12; m++){ aR[wrp*384 + kb+m] = acc[m].x; aI[wrp*384 + kb+m] = acc[m].y; }
    __syncthreads();
    float lam = *lam_p;
    const float sc = 1.0f / 384.0f;   // ortho ifft2 total = unnormalized-inverse / 384
    float rr = 0.f;
    int t = threadIdx.x;
    #pragma unroll
    for (int e = 3*t; e < 3*t+3; e++){
        float ar = aR[e] + aR[384+e] + aR[768+e] + aR[1152+e];
        float ai = aI[e] + aI[384+e] + aI[768+e] + aI[1152+e];
        int idx = bh*WW + e;
        float2 rhs = make_float2(fmaf(lam, xre[idx], ar*sc), fmaf(lam, xim[idx], ai*sc));
        g_r[idx] = rhs; g_p[idx] = rhs;
        out[idx] = make_float2(0.f, 0.f);
        rr += rhs.x*rhs.x + rhs.y*rhs.y;
    }
    float tot = block_reduce(rr, sred, 4);
    if (t == 0) g_part_rr[bh] = tot;
}

// ---------------- init rTr[0] ----------------
__global__ void __launch_bounds__(384) k_reduce_init(){
    __shared__ float sred[16];
    int b = blockIdx.x;
    float v = g_part_rr[b*HH + threadIdx.x];
    float tot = block_reduce(v, sred, 12);
    if (threadIdx.x == 0) g_rtr2[b] = tot;   // slot 0
}

// ---------------- update x,r ----------------
__global__ void __launch_bounds__(384) k_update_xr(float2* __restrict__ out, int cur){
    __shared__ float sred[16];
    __shared__ float s_alpha;
    int bh = blockIdx.x; int b = bh / HH;
    float v = g_part_pap[b*HH + threadIdx.x];
    float pap = block_reduce(v, sred, 12);
    if (threadIdx.x == 0) s_alpha = g_rtr2[cur*BB + b] / pap;
    __syncthreads();
    float a = s_alpha;
    int i = bh*WW + threadIdx.x;
    float2 p = g_p[i], ap = g_Ap[i], x = out[i], r = g_r[i];
    x.x = fmaf(a, p.x, x.x);   x.y = fmaf(a, p.y, x.y);
    r.x = fmaf(-a, ap.x, r.x); r.y = fmaf(-a, ap.y, r.y);
    out[i] = x; g_r[i] = r;
    float rr = fmaf(r.x, r.x, r.y*r.y);
    float tot = block_reduce(rr, sred, 12);
    if (threadIdx.x == 0) g_part_rr[bh] = tot;
}

// ---------------- update p ----------------
__global__ void __launch_bounds__(384) k_update_p(int cur){
    __shared__ float sred[16];
    __shared__ float s_beta;
    int bh = blockIdx.x; int b = bh / HH, h = bh % HH;
    float v = g_part_rr[b*HH + threadIdx.x];
    float rtrNew = block_reduce(v, sred, 12);
    if (threadIdx.x == 0){
        s_beta = rtrNew / g_rtr2[cur*BB + b];
        if (h == 0) g_rtr2[(cur^1)*BB + b] = rtrNew;
    }
    __syncthreads();
    float be = s_beta;
    int i = bh*WW + threadIdx.x;
    float2 r = g_r[i], p = g_p[i];
    g_p[i] = make_float2(fmaf(be, p.x, r.x), fmaf(be, p.y, r.y));
}

// ---------------- launch ----------------
extern "C" void kernel_launch(void* const* d_in, const int* in_sizes, int n_in,
                              void* d_out, int out_size){
    (void)in_sizes; (void)n_in; (void)out_size;
    const float* lam  = (const float*)d_in[0];
    const float* xre  = (const float*)d_in[1];
    const float* xim  = (const float*)d_in[2];
    const float* yre  = (const float*)d_in[3];
    const float* yim  = (const float*)d_in[4];
    const float* sre  = (const float*)d_in[5];
    const float* sim  = (const float*)d_in[6];
    const float* mask = (const float*)d_in[7];
    float2* out = (float2*)d_out;

    k_init_tw<<<1, 384>>>();
    k_init_maskp<<<BB*HH, 384>>>(mask);
    k_rhs1<<<BB*CC*48, 256>>>(yre, yim, mask);
    k_rhs2<<<BB*HH, 128>>>(sre, sim, xre, xim, lam, out);
    k_reduce_init<<<BB, 384>>>();

    for (int it = 0; it < 10; it++){
        int cur = it & 1;
        k_pass1<<<BB*CC*HH/8, 256>>>(sre, sim);
        k_pass2<<<BB*CC*48, 256>>>();
        k_pass3<<<BB*HH, 128>>>(sre, sim, lam);
        k_update_xr<<<BB*HH, 384>>>(out, cur);
        k_update_p<<<BB*HH, 384>>>(cur);
    }
}